// round 16
// baseline (speedup 1.0000x reference)
#include <cuda_runtime.h>
#include <cstdint>

constexpr int B = 8192;    // batch
constexpr int D = 4096;    // features
constexpr int H = 2048;    // hidden
constexpr int HW = H / 32; // 64 packed words

// Device-global scratch (no runtime allocation allowed)
__device__ uint32_t g_Wcols[D * HW];     // Wb column d packed along h (1 MB)
__device__ float    g_template[D];       // layer-2 output row for all-ones h
__device__ uint32_t g_m1[HW], g_m2[HW], g_m3[HW], g_m4[HW], g_mall[HW];
__device__ int      g_t2[D];
__device__ int      g_t1u;               // uniform layer-1 threshold in {1,2}, else -1

// ---------------------------------------------------------------------------
// Kernel 1: pack W + template + t2 (blocks 0..127) and masks/t1u (block 128).
// (Round-14 proven version, unchanged.)
// ---------------------------------------------------------------------------
__global__ void __launch_bounds__(512) pack_kernel(const float* __restrict__ W,
                                                   const float* __restrict__ be,
                                                   const float* __restrict__ b0,
                                                   const float* __restrict__ b3) {
    if (blockIdx.x < 128) {
        __shared__ uint32_t s[32][65];    // [col][word], stride 65: conflict-free
        __shared__ int scnt[32][16];      // per-col popc partials per warp
        int t    = threadIdx.x;
        int lane = t & 31;                // column
        int wg   = t >> 5;                // warp 0..15, owns words wg*4..wg*4+3
        int d0   = blockIdx.x * 32;

        int pcnt = 0;
#pragma unroll
        for (int k = 0; k < 4; k++) {
            int w = wg * 4 + k;           // word index, rows w*32..w*32+31
            const float* Wp = W + (size_t)(w * 32) * D + d0 + lane;
            float fv[32];
#pragma unroll
            for (int r = 0; r < 32; r++)  // 32 independent coalesced loads
                fv[r] = __ldcs(Wp + (size_t)r * D);
            uint32_t u = 0;
#pragma unroll
            for (int r = 0; r < 32; r++)
                if (fv[r] >= 0.5f) u |= (1u << r);
            s[lane][w] = u;
            pcnt += __popc(u);
        }
        scnt[lane][wg] = pcnt;
        __syncthreads();

        // Store Wcols: 512 threads write 512 uint4 (full-sector writes, 1 MB).
        {
            int col = t >> 4, j = t & 15;
            uint4 v = make_uint4(s[col][j * 4 + 0], s[col][j * 4 + 1],
                                 s[col][j * 4 + 2], s[col][j * 4 + 3]);
            reinterpret_cast<uint4*>(g_Wcols)[(size_t)(d0 + col) * 16 + j] = v;
        }

        // Template + t2 for this block's 32 columns.
        if (t < 32) {
            int c = 0;
#pragma unroll
            for (int wgi = 0; wgi < 16; wgi++) c += scnt[t][wgi];
            int d = d0 + t;
            int t2 = (int)ceilf(1.0f - b3[d]);
            g_t2[d] = t2;
            g_template[d] = (c >= t2) ? 1.0f : 0.0f;
        }
    } else {
        // Block 128: layer-1 threshold masks + uniformity flag.
        __shared__ int s_ok;
        int t = threadIdx.x;
        if (t == 0) s_ok = 1;
        __syncthreads();

        int t0 = (int)ceilf(1.0f - be[0] - b0[0]);

        if (t < HW) {
            uint32_t m1 = 0, m2 = 0, m3 = 0, m4 = 0, mall = 0;
#pragma unroll
            for (int bit = 0; bit < 32; bit++) {
                int h = t * 32 + bit;
                int ti = (int)ceilf(1.0f - be[h] - b0[h]);
                uint32_t m = 1u << bit;
                if (ti <= 0)      mall |= m;
                else if (ti == 1) m1 |= m;
                else if (ti == 2) m2 |= m;
                else if (ti == 3) m3 |= m;
                else if (ti == 4) m4 |= m;
            }
            g_m1[t] = m1; g_m2[t] = m2; g_m3[t] = m3; g_m4[t] = m4; g_mall[t] = mall;
        }

        int ok = 1;
        for (int h = t; h < H; h += 512) {
            int ti = (int)ceilf(1.0f - be[h] - b0[h]);
            if (ti != t0) ok = 0;
        }
        if (!ok) s_ok = 0;   // benign race, all writers store 0
        __syncthreads();
        if (t == 0) g_t1u = (s_ok && t0 >= 1 && t0 <= 2) ? t0 : -1;
    }
}

// ---------------------------------------------------------------------------
// Kernel 2 (fused layer1+layer2): one warp per batch row, 8 rows per block.
// NEW: 256-column double-chunks -> 8 ballot masks; inner round extracts one
// bit from EACH mask = 8 independent Wcols loads in flight (was 4), and the
// serialized sat-check chain halves (16 iterations vs 32).
// ---------------------------------------------------------------------------
__global__ void __launch_bounds__(256) fused_kernel(const float* __restrict__ x,
                                                    float* __restrict__ out) {
    __shared__ uint32_t sh_h[8][HW];   // slow-path h bits (rarely used)
    __shared__ int sflag[8];           // per-row "broadcast template" flag
    int tid  = threadIdx.x;
    int warp = tid >> 5;
    int lane = tid & 31;
    int b = blockIdx.x * 8 + warp;

    // Preload template slice into registers (pack_kernel already ran).
    const float4* tp = reinterpret_cast<const float4*>(g_template);
    float4 tpl0 = __ldg(&tp[tid]);
    float4 tpl1 = __ldg(&tp[tid + 256]);
    float4 tpl2 = __ldg(&tp[tid + 512]);
    float4 tpl3 = __ldg(&tp[tid + 768]);

    const float4* xr = reinterpret_cast<const float4*>(x + (size_t)b * D);
    const uint2*  Wc = reinterpret_cast<const uint2*>(g_Wcols);
    int uni = g_t1u;

    uint2 c1 = make_uint2(0u, 0u), c2 = make_uint2(0u, 0u);
    uint2 c3 = make_uint2(0u, 0u), c4 = make_uint2(0u, 0u);
    bool sat = false;

    float4 f0 = xr[lane];                      // prefetch double-chunk 0
    float4 f1 = xr[32 + lane];
    for (int i = 0; i < 16; i++) {             // 16 double-chunks of 256 cols
        float4 cur0 = f0, cur1 = f1;
        if (i + 1 < 16) {                      // prefetch next double-chunk
            f0 = xr[(2 * i + 2) * 32 + lane];
            f1 = xr[(2 * i + 3) * 32 + lane];
        }

        uint32_t m[8];
        m[0] = __ballot_sync(0xffffffffu, cur0.x != 0.0f);
        m[1] = __ballot_sync(0xffffffffu, cur0.y != 0.0f);
        m[2] = __ballot_sync(0xffffffffu, cur0.z != 0.0f);
        m[3] = __ballot_sync(0xffffffffu, cur0.w != 0.0f);
        m[4] = __ballot_sync(0xffffffffu, cur1.x != 0.0f);
        m[5] = __ballot_sync(0xffffffffu, cur1.y != 0.0f);
        m[6] = __ballot_sync(0xffffffffu, cur1.z != 0.0f);
        m[7] = __ballot_sync(0xffffffffu, cur1.w != 0.0f);
        int base = i * 256;
        // column for mask j, bit l:  base + (j>>2)*128 + l*4 + (j&3)

        if (uni >= 1) {
            // 2-plane CSA; up to 8 independent predicated loads per round.
            while (m[0] | m[1] | m[2] | m[3] | m[4] | m[5] | m[6] | m[7]) {
                uint2 v[8];
                bool  p[8];
#pragma unroll
                for (int j = 0; j < 8; j++) {
                    p[j] = (m[j] != 0);
                    if (p[j]) {
                        int l = __ffs(m[j]) - 1; m[j] &= m[j] - 1;
                        v[j] = Wc[(base + ((j >> 2) << 7) + l * 4 + (j & 3)) * 32 + lane];
                    }
                }
#pragma unroll
                for (int j = 0; j < 8; j++) {
                    if (p[j]) {
                        c2.x |= c1.x & v[j].x; c1.x |= v[j].x;
                        c2.y |= c1.y & v[j].y; c1.y |= v[j].y;
                    }
                }
            }
            uint32_t sw = (uni == 1) ? (c1.x & c1.y) : (c2.x & c2.y);
            if (__all_sync(0xffffffffu, sw == 0xffffffffu)) { sat = true; break; }
        } else {
            // general 4-plane saturating CSA (rare path, simple serial form)
#pragma unroll
            for (int j = 0; j < 8; j++) {
                uint32_t mm = m[j];
                while (mm) {
                    int l = __ffs(mm) - 1; mm &= mm - 1;
                    uint2 v = Wc[(base + ((j >> 2) << 7) + l * 4 + (j & 3)) * 32 + lane];
                    c4.x |= c3.x & v.x; c3.x |= c2.x & v.x; c2.x |= c1.x & v.x; c1.x |= v.x;
                    c4.y |= c3.y & v.y; c3.y |= c2.y & v.y; c2.y |= c1.y & v.y; c1.y |= v.y;
                }
            }
            if (__all_sync(0xffffffffu, (c4.x & c4.y) == 0xffffffffu)) break;
        }
    }

    // Resolve hidden bits for this row
    uint2 hw;
    if (uni >= 1) {
        hw = sat ? make_uint2(0xffffffffu, 0xffffffffu) : ((uni == 1) ? c1 : c2);
    } else {
        int w0 = 2 * lane, w1 = 2 * lane + 1;
        hw.x = g_mall[w0] | (c1.x & g_m1[w0]) | (c2.x & g_m2[w0]) |
               (c3.x & g_m3[w0]) | (c4.x & g_m4[w0]);
        hw.y = g_mall[w1] | (c1.y & g_m1[w1]) | (c2.y & g_m2[w1]) |
               (c3.y & g_m3[w1]) | (c4.y & g_m4[w1]);
    }
    bool allones = __all_sync(0xffffffffu, (hw.x & hw.y) == 0xffffffffu);
    if (lane == 0) sflag[warp] = allones ? 1 : 0;

    if (!allones) {
        // exact path (rare): popcount h against every Wb column
        sh_h[warp][2 * lane]     = hw.x;
        sh_h[warp][2 * lane + 1] = hw.y;
        __syncwarp();
        const uint32_t* hv = sh_h[warp];
        for (int k = 0; k < D / 32; k++) {
            int d = k * 32 + lane;
            int t2 = g_t2[d];
            float val;
            if (t2 <= 0) {
                val = 1.0f;
            } else {
                const uint32_t* wv = g_Wcols + (size_t)d * HW;
                int c = 0;
                for (int w = 0; w < HW; w++) {
                    c += __popc(hv[w] & wv[w]);
                    if (c >= t2) break;
                }
                val = (c >= t2) ? 1.0f : 0.0f;
            }
            out[(size_t)b * D + d] = val;
        }
    }
    __syncthreads();

    // Block-cooperative template broadcast: pure streaming stores from regs.
#pragma unroll
    for (int r = 0; r < 8; r++) {
        if (sflag[r]) {
            float4* orow = reinterpret_cast<float4*>(out + (size_t)(blockIdx.x * 8 + r) * D);
            __stcs(&orow[tid],       tpl0);
            __stcs(&orow[tid + 256], tpl1);
            __stcs(&orow[tid + 512], tpl2);
            __stcs(&orow[tid + 768], tpl3);
        }
    }
}

// ---------------------------------------------------------------------------
extern "C" void kernel_launch(void* const* d_in, const int* in_sizes, int n_in,
                              void* d_out, int out_size) {
    const float* x     = (const float*)d_in[0];  // [B, D]
    const float* W     = (const float*)d_in[1];  // [H, D]
    const float* b_enc = (const float*)d_in[2];  // [H]
    const float* b0    = (const float*)d_in[3];  // [H]
    const float* b3    = (const float*)d_in[4];  // [D]
    float* out = (float*)d_out;                  // [B, D]

    pack_kernel<<<129, 512>>>(W, b_enc, b0, b3);
    fused_kernel<<<B / 8, 256>>>(x, out);
}